// round 8
// baseline (speedup 1.0000x reference)
#include <cuda_runtime.h>
#include <cstdint>
typedef unsigned long long ull;
typedef unsigned int u32;

#define TT 128
#define NQ8 37    // KG/8, KG=296
#define XS 152    // parity-array row stride (floats); 148 used
#define US 132
#define NT 512

// bf16-packed gate weights: uint4 per (k8-chunk, gate row). Word i holds
// (w_even bf16 in low16, compensated-high bf16 in high16).
__device__ __align__(16) uint4 Wgb[NQ8 * 1024];
__device__ __align__(16) float W1_perm[64 * 128 * 4];   // parity-ordered k
__device__ __align__(16) float W2_perm[32 * 128 * 4];
__device__ __align__(16) float Wz_perm[32 * 64 * 4];

__device__ __forceinline__ void fma2(ull &d, ull a, ull b) {
    asm("fma.rn.f32x2 %0, %1, %2, %0;" : "+l"(d) : "l"(a), "l"(b));
}
__device__ __forceinline__ float hsum2(ull v) {
    float lo, hi; asm("mov.b64 {%0, %1}, %2;" : "=f"(lo), "=f"(hi) : "l"(v));
    return lo + hi;
}
__device__ __forceinline__ ull pk(u32 lo, u32 hi) {
    ull r; asm("mov.b64 %0, {%1, %2};" : "=l"(r) : "r"(lo), "r"(hi)); return r;
}
__device__ __forceinline__ float fsig(float x) { return 1.f / (1.f + __expf(-x)); }
__device__ __forceinline__ float ftanh_(float x) { return fmaf(2.f, fsig(2.f * x), -1.f); }

__device__ __forceinline__ float gw(const float* W_ih, const float* W_hh, int R, int k) {
    return (k < 40) ? W_ih[R * 40 + k] : W_hh[R * 256 + (k - 40)];
}

__global__ void permute_weights(const float* __restrict__ W_ih, const float* __restrict__ W_hh,
                                const float* __restrict__ W1, const float* __restrict__ W2,
                                const float* __restrict__ Wz)
{
    const int stride = gridDim.x * blockDim.x;
    const int tid = blockIdx.x * blockDim.x + threadIdx.x;
    // gate pack: word index i -> (q8 = i>>12, R = (i>>2)&1023, pair i&3)
    for (int i = tid; i < NQ8 * 1024 * 4; i += stride) {
        int i4 = i & 3, R = (i >> 2) & 1023, q8 = i >> 12;
        int k0 = q8 * 8 + i4 * 2;
        float w0 = gw(W_ih, W_hh, R, k0);
        float w1 = gw(W_ih, W_hh, R, k0 + 1);
        u32 b0 = __float_as_uint(w0);
        u32 lo = (b0 + 0x7FFFu + ((b0 >> 16) & 1u)) >> 16;   // bf16 RNE of even weight
        u32 hb = __float_as_uint(w1) >> 16;
        // choose high bf16 so the full 32-bit pattern best approximates w1
        u32 best = (hb << 16) | lo;
        float be = fabsf(__uint_as_float(best) - w1);
        #pragma unroll
        for (int d = -1; d <= 1; d += 2) {
            u32 cand = ((hb + (u32)d) << 16) | lo;
            float e = fabsf(__uint_as_float(cand) - w1);
            if (e < be) { be = e; best = cand; }
        }
        ((u32*)Wgb)[i] = best;
    }
    // W1: parity-ordered k (first 32 chunks even k, then odd)
    for (int i = tid; i < 64 * 128 * 4; i += stride) {
        int j = i & 3, m = (i >> 2) & 127, kp = i >> 9;
        int k = (kp < 32) ? 2 * (4 * kp + j) : 2 * (4 * (kp - 32) + j) + 1;
        W1_perm[i] = W1[m * 256 + k];
    }
    for (int i = tid; i < 32 * 128 * 4; i += stride) {
        int j = i & 3, m = (i >> 2) & 127, k4 = i >> 9;
        W2_perm[i] = W2[m * 128 + 4 * k4 + j];
    }
    for (int i = tid; i < 32 * 64 * 4; i += stride) {
        int j = i & 3, m = (i >> 2) & 63, k4 = i >> 8;
        Wz_perm[i] = Wz[m * 128 + 4 * k4 + j];
    }
}

// One CTA = 8 batch rows, 512 threads. Thread (hid=tid>>1, bq=tid&1): all 4
// gates of `hid` for batch rows bq*4+j. Activations split by k-parity:
// xev[m]: col 2m, xod[m]: col 2m+1  (cols: a 0..7 | z 8..39 | h 40..295)
__global__ void __launch_bounds__(NT, 1)
lstm_guide_kernel(const float* __restrict__ A, const float* __restrict__ eps,
                  const float* __restrict__ z0, const float* __restrict__ h0,
                  const float* __restrict__ c0, const float* __restrict__ b_ih,
                  const float* __restrict__ b_hh, const float* __restrict__ b1,
                  const float* __restrict__ b2, const float* __restrict__ bz,
                  float* __restrict__ Z)
{
    __shared__ __align__(16) float xev[8 * XS];
    __shared__ __align__(16) float xod[8 * XS];
    __shared__ __align__(16) float u1s[8 * US];
    __shared__ __align__(16) float u2s[8 * US];
    __shared__ __align__(16) float zzs[8 * 64];

    const int tid = threadIdx.x;
    const int n0 = blockIdx.x * 8;
    const int hid = tid >> 1, bq = tid & 1;

    const float bs0 = b_ih[hid]       + b_hh[hid];
    const float bs1 = b_ih[256 + hid] + b_hh[256 + hid];
    const float bs2 = b_ih[512 + hid] + b_hh[512 + hid];
    const float bs3 = b_ih[768 + hid] + b_hh[768 + hid];
    const float b1v = b1[tid & 127], b2v = b2[tid & 127], bzv = bz[tid & 63];

    for (int i = tid; i < 8 * 256; i += NT) {       // h0 -> cols 40+k
        int b = i >> 8, k = i & 255;
        float* arr = (k & 1) ? xod : xev;
        arr[b * XS + 20 + (k >> 1)] = h0[k];
    }
    if (tid < 64) {                                 // a0 -> cols k
        int b = tid >> 3, k = tid & 7;
        float* arr = (k & 1) ? xod : xev;
        arr[b * XS + (k >> 1)] = A[((n0 + b) * TT) * 8 + k];
    } else if (tid < 320) {                         // z0 -> cols 8+j
        int i = tid - 64, b = i >> 5, j = i & 31;
        float* arr = (j & 1) ? xod : xev;
        arr[b * XS + 4 + (j >> 1)] = z0[j];
    }
    float c_reg[4];
    #pragma unroll
    for (int j = 0; j < 4; ++j) c_reg[j] = c0[hid];
    __syncthreads();

    const uint4* wg = Wgb + hid;

    for (int t = 0; t < TT; ++t) {
        // ===== gates =====
        ull acc[4][4];
        #pragma unroll
        for (int g = 0; g < 4; ++g)
            #pragma unroll
            for (int j = 0; j < 4; ++j) acc[g][j] = 0ull;

        for (int q = 0; q < NQ8; ++q) {
            uint4 W[4];
            W[0] = __ldg(wg + q * 1024);
            W[1] = __ldg(wg + q * 1024 + 256);
            W[2] = __ldg(wg + q * 1024 + 512);
            W[3] = __ldg(wg + q * 1024 + 768);
            ull oda[4], odb[4], eva[4], evb[4];
            #pragma unroll
            for (int g = 0; g < 4; ++g) {
                oda[g] = pk(W[g].x, W[g].y);              // (w1+eps, w3+eps) as fp32
                odb[g] = pk(W[g].z, W[g].w);              // (w5, w7)
                eva[g] = pk(W[g].x << 16, W[g].y << 16);  // (w0, w2) exact bf16
                evb[g] = pk(W[g].z << 16, W[g].w << 16);  // (w4, w6)
            }
            #pragma unroll
            for (int j = 0; j < 4; ++j) {
                const int row = (bq * 4 + j) * XS + 4 * q;
                const ulonglong2 xe = *(const ulonglong2*)(xev + row);
                const ulonglong2 xo = *(const ulonglong2*)(xod + row);
                #pragma unroll
                for (int g = 0; g < 4; ++g) {
                    fma2(acc[g][j], eva[g], xe.x); fma2(acc[g][j], oda[g], xo.x);
                    fma2(acc[g][j], evb[g], xe.y); fma2(acc[g][j], odb[g], xo.y);
                }
            }
        }

        // ===== LSTM cell =====
        float hv[4];
        #pragma unroll
        for (int j = 0; j < 4; ++j) {
            float iv = fsig(hsum2(acc[0][j]) + bs0);
            float fv = fsig(hsum2(acc[1][j]) + bs1);
            float gv = ftanh_(hsum2(acc[2][j]) + bs2);
            float ov = fsig(hsum2(acc[3][j]) + bs3);
            float c = fv * c_reg[j] + iv * gv;
            c_reg[j] = c;
            hv[j] = ov * ftanh_(c);
        }
        __syncthreads();

        // write h_{t+1} (col 40+hid -> parity arr idx 20+hid/2); prefetch a_{t+1}
        {
            float* harr = (hid & 1) ? xod : xev;
            const int hw = 20 + (hid >> 1);
            #pragma unroll
            for (int j = 0; j < 4; ++j) harr[(bq * 4 + j) * XS + hw] = hv[j];
        }
        if (tid < 64 && t + 1 < TT) {
            int b = tid >> 3, k = tid & 7;
            float* arr = (k & 1) ? xod : xev;
            arr[b * XS + (k >> 1)] = A[((n0 + b) * TT + t + 1) * 8 + k];
        }
        __syncthreads();

        // ===== MLP1: relu(h @ W1^T + b1), parity streams =====
        {
            const int m = tid & 127, q = tid >> 7;
            const float* e0 = xev + (2 * q) * XS + 20;
            const float* e1 = e0 + XS;
            const float* o0 = xod + (2 * q) * XS + 20;
            const float* o1 = o0 + XS;
            ull a0 = 0ull, a1 = 0ull;
            #pragma unroll 4
            for (int kp = 0; kp < 32; ++kp) {
                const ulonglong2 wv = __ldg((const ulonglong2*)(W1_perm + ((kp << 7) + m) * 4));
                const ulonglong2 p0 = *(const ulonglong2*)(e0 + 4 * kp);
                const ulonglong2 p1 = *(const ulonglong2*)(e1 + 4 * kp);
                fma2(a0, wv.x, p0.x); fma2(a0, wv.y, p0.y);
                fma2(a1, wv.x, p1.x); fma2(a1, wv.y, p1.y);
            }
            #pragma unroll 4
            for (int kp = 0; kp < 32; ++kp) {
                const ulonglong2 wv = __ldg((const ulonglong2*)(W1_perm + (((kp + 32) << 7) + m) * 4));
                const ulonglong2 p0 = *(const ulonglong2*)(o0 + 4 * kp);
                const ulonglong2 p1 = *(const ulonglong2*)(o1 + 4 * kp);
                fma2(a0, wv.x, p0.x); fma2(a0, wv.y, p0.y);
                fma2(a1, wv.x, p1.x); fma2(a1, wv.y, p1.y);
            }
            u1s[(2 * q) * US + m]     = fmaxf(hsum2(a0) + b1v, 0.f);
            u1s[(2 * q + 1) * US + m] = fmaxf(hsum2(a1) + b1v, 0.f);
        }
        __syncthreads();

        // ===== MLP2 =====
        {
            const int m = tid & 127, q = tid >> 7;
            const float* x0 = u1s + (2 * q) * US;
            const float* x1 = x0 + US;
            ull a0 = 0ull, a1 = 0ull;
            #pragma unroll 4
            for (int k4 = 0; k4 < 32; ++k4) {
                const ulonglong2 wv = __ldg((const ulonglong2*)(W2_perm + ((k4 << 7) + m) * 4));
                const ulonglong2 p0 = *(const ulonglong2*)(x0 + 4 * k4);
                const ulonglong2 p1 = *(const ulonglong2*)(x1 + 4 * k4);
                fma2(a0, wv.x, p0.x); fma2(a0, wv.y, p0.y);
                fma2(a1, wv.x, p1.x); fma2(a1, wv.y, p1.y);
            }
            u2s[(2 * q) * US + m]     = fmaxf(hsum2(a0) + b2v, 0.f);
            u2s[(2 * q + 1) * US + m] = fmaxf(hsum2(a1) + b2v, 0.f);
        }
        __syncthreads();

        // ===== zz = u2 @ Wz^T + bz =====
        {
            const int jz = tid & 63, rz = tid >> 6;
            const float* xp = u2s + rz * US;
            ull a0 = 0ull;
            #pragma unroll 4
            for (int k4 = 0; k4 < 32; ++k4) {
                const ulonglong2 wv = __ldg((const ulonglong2*)(Wz_perm + ((k4 << 6) + jz) * 4));
                const ulonglong2 pv = *(const ulonglong2*)(xp + 4 * k4);
                fma2(a0, wv.x, pv.x); fma2(a0, wv.y, pv.y);
            }
            zzs[rz * 64 + jz] = hsum2(a0) + bzv;
        }
        __syncthreads();

        // ===== z_t = loc + softplus(raw) * eps =====
        if (tid < 256) {
            const int j = tid & 31, r = tid >> 5;
            float loc = zzs[r * 64 + j];
            float sr  = zzs[r * 64 + 32 + j];
            float sp  = (sr > 15.f) ? sr : log1pf(__expf(sr));
            float e   = eps[((n0 + r) * TT + t) * 32 + j];
            float zn  = fmaf(sp, e, loc);
            Z[((n0 + r) * TT + t) * 32 + j] = zn;
            float* arr = (j & 1) ? xod : xev;
            arr[r * XS + 4 + (j >> 1)] = zn;
        }
        __syncthreads();
    }
}

extern "C" void kernel_launch(void* const* d_in, const int* in_sizes, int n_in,
                              void* d_out, int out_size) {
    const float* A    = (const float*)d_in[0];
    const float* eps  = (const float*)d_in[1];
    const float* z0   = (const float*)d_in[2];
    const float* h0   = (const float*)d_in[3];
    const float* c0   = (const float*)d_in[4];
    const float* W_ih = (const float*)d_in[5];
    const float* W_hh = (const float*)d_in[6];
    const float* b_ih = (const float*)d_in[7];
    const float* b_hh = (const float*)d_in[8];
    const float* W1   = (const float*)d_in[9];
    const float* b1   = (const float*)d_in[10];
    const float* W2   = (const float*)d_in[11];
    const float* b2   = (const float*)d_in[12];
    const float* Wz   = (const float*)d_in[13];
    const float* bz   = (const float*)d_in[14];

    permute_weights<<<148, 256>>>(W_ih, W_hh, W1, W2, Wz);
    lstm_guide_kernel<<<128, NT>>>(A, eps, z0, h0, c0,
                                   b_ih, b_hh, b1, b2, bz, (float*)d_out);
}

// round 9
// speedup vs baseline: 1.0066x; 1.0066x over previous
#include <cuda_runtime.h>
typedef unsigned long long ull;

#define TT 128
#define ZD 32
#define KG4 74
#define KGP 300   // xh row stride (floats): a 0..7 | z 8..39 | h 40..295
#define US 132
#define NT 512

__device__ __align__(16) float Wg_perm[KG4 * 1024 * 4];  // [k4][1024 rows][4]
__device__ __align__(16) float W1_perm[64 * 128 * 4];
__device__ __align__(16) float W2_perm[32 * 128 * 4];
__device__ __align__(16) float Wz_perm[32 * 64 * 4];

__device__ __forceinline__ void fma2(ull &d, ull a, ull b) {
    asm("fma.rn.f32x2 %0, %1, %2, %0;" : "+l"(d) : "l"(a), "l"(b));
}
__device__ __forceinline__ float hsum2(ull v) {
    float lo, hi; asm("mov.b64 {%0, %1}, %2;" : "=f"(lo), "=f"(hi) : "l"(v));
    return lo + hi;
}
__device__ __forceinline__ float fsig(float x) { return 1.f / (1.f + __expf(-x)); }
__device__ __forceinline__ float ftanh_(float x) { return fmaf(2.f, fsig(2.f * x), -1.f); }

__global__ void permute_weights(const float* __restrict__ W_ih, const float* __restrict__ W_hh,
                                const float* __restrict__ W1, const float* __restrict__ W2,
                                const float* __restrict__ Wz)
{
    const int stride = gridDim.x * blockDim.x;
    const int tid = blockIdx.x * blockDim.x + threadIdx.x;
    for (int i = tid; i < KG4 * 1024 * 4; i += stride) {
        int j = i & 3, R = (i >> 2) & 1023, k4 = i >> 12;
        int k = 4 * k4 + j;
        Wg_perm[i] = (k < 40) ? W_ih[R * 40 + k] : W_hh[R * 256 + (k - 40)];
    }
    for (int i = tid; i < 64 * 128 * 4; i += stride) {
        int j = i & 3, m = (i >> 2) & 127, k4 = i >> 9;
        W1_perm[i] = W1[m * 256 + 4 * k4 + j];
    }
    for (int i = tid; i < 32 * 128 * 4; i += stride) {
        int j = i & 3, m = (i >> 2) & 127, k4 = i >> 9;
        W2_perm[i] = W2[m * 128 + 4 * k4 + j];
    }
    for (int i = tid; i < 32 * 64 * 4; i += stride) {
        int j = i & 3, m = (i >> 2) & 63, k4 = i >> 8;
        Wz_perm[i] = Wz[m * 128 + 4 * k4 + j];
    }
}

#define LDW(dst, kk) do { \
    dst[0] = __ldg((const ulonglong2*)(wb + ((kk) * 1024 +   0) * 4)); \
    dst[1] = __ldg((const ulonglong2*)(wb + ((kk) * 1024 + 256) * 4)); \
    dst[2] = __ldg((const ulonglong2*)(wb + ((kk) * 1024 + 512) * 4)); \
    dst[3] = __ldg((const ulonglong2*)(wb + ((kk) * 1024 + 768) * 4)); \
} while (0)

#define GEMM4(W, kk) do { \
    _Pragma("unroll") \
    for (int j = 0; j < 4; ++j) { \
        const ulonglong2 xv = *(const ulonglong2*)(xc + (bq * 4 + j) * KGP + 4 * (kk)); \
        fma2(acc[0][j], W[0].x, xv.x); fma2(acc[0][j], W[0].y, xv.y); \
        fma2(acc[1][j], W[1].x, xv.x); fma2(acc[1][j], W[1].y, xv.y); \
        fma2(acc[2][j], W[2].x, xv.x); fma2(acc[2][j], W[2].y, xv.y); \
        fma2(acc[3][j], W[3].x, xv.x); fma2(acc[3][j], W[3].y, xv.y); \
    } \
} while (0)

// One CTA = 8 batch rows, 512 threads. Thread (hid=tid>>1, bq=tid&1) computes
// all 4 gates of `hid` for 4 batch rows. Ping-pong xh; 4 syncthreads/step.
__global__ void __launch_bounds__(NT, 1)
lstm_guide_kernel(const float* __restrict__ A, const float* __restrict__ eps,
                  const float* __restrict__ z0, const float* __restrict__ h0,
                  const float* __restrict__ c0, const float* __restrict__ b_ih,
                  const float* __restrict__ b_hh, const float* __restrict__ b1,
                  const float* __restrict__ b2, const float* __restrict__ bz,
                  float* __restrict__ Z)
{
    __shared__ __align__(16) float xh[2 * 8 * KGP];
    __shared__ __align__(16) float u1s[8 * US];
    __shared__ __align__(16) float u2s[8 * US];

    const int tid = threadIdx.x;
    const int n0 = blockIdx.x * 8;
    const int hid = tid >> 1, bq = tid & 1;

    const float bs0 = b_ih[hid]       + b_hh[hid];
    const float bs1 = b_ih[256 + hid] + b_hh[256 + hid];
    const float bs2 = b_ih[512 + hid] + b_hh[512 + hid];
    const float bs3 = b_ih[768 + hid] + b_hh[768 + hid];
    const float b1v = b1[tid & 127], b2v = b2[tid & 127];
    const float bz0 = bz[tid & 31], bz1 = bz[32 + (tid & 31)];

    for (int i = tid; i < 8 * 256; i += NT) {       // h0 -> buf0
        int b = i >> 8, k = i & 255;
        xh[b * KGP + 40 + k] = h0[k];
    }
    if (tid < 64) {                                 // a0
        int b = tid >> 3, k = tid & 7;
        xh[b * KGP + k] = A[((n0 + b) * TT) * 8 + k];
    } else if (tid < 320) {                         // z0
        int i = tid - 64, b = i >> 5, j = i & 31;
        xh[b * KGP + 8 + j] = z0[j];
    }
    float c_reg[4];
    #pragma unroll
    for (int j = 0; j < 4; ++j) c_reg[j] = c0[hid];
    __syncthreads();

    const float* wb = Wg_perm + hid * 4;

    for (int t = 0; t < TT; ++t) {
        float* xc = xh + (t & 1) * 8 * KGP;
        float* xn = xh + ((t + 1) & 1) * 8 * KGP;

        // ===== gates: software-pipelined weight prefetch =====
        ull acc[4][4];
        #pragma unroll
        for (int g = 0; g < 4; ++g)
            #pragma unroll
            for (int j = 0; j < 4; ++j) acc[g][j] = 0ull;

        ulonglong2 WA[4], WB[4];
        LDW(WA, 0);
        #pragma unroll 1
        for (int k4 = 0; k4 < KG4 - 2; k4 += 2) {
            LDW(WB, k4 + 1);
            GEMM4(WA, k4);
            LDW(WA, k4 + 2);
            GEMM4(WB, k4 + 1);
        }
        LDW(WB, KG4 - 1);
        GEMM4(WA, KG4 - 2);
        GEMM4(WB, KG4 - 1);

        // ===== LSTM cell (all 4 gates in-thread) =====
        float hv[4];
        #pragma unroll
        for (int j = 0; j < 4; ++j) {
            float iv = fsig(hsum2(acc[0][j]) + bs0);
            float fv = fsig(hsum2(acc[1][j]) + bs1);
            float gv = ftanh_(hsum2(acc[2][j]) + bs2);
            float ov = fsig(hsum2(acc[3][j]) + bs3);
            float c = fv * c_reg[j] + iv * gv;
            c_reg[j] = c;
            hv[j] = ov * ftanh_(c);
        }
        // h_{t+1} into NEXT buffer (no barrier needed before writes)
        #pragma unroll
        for (int j = 0; j < 4; ++j)
            xn[(bq * 4 + j) * KGP + 40 + hid] = hv[j];
        if (tid < 64 && t + 1 < TT) {               // a_{t+1} prefetch
            int b = tid >> 3, k = tid & 7;
            xn[b * KGP + k] = A[((n0 + b) * TT + t + 1) * 8 + k];
        }
        __syncthreads();                            // sync 1: h complete

        // ===== MLP1: relu(h @ W1^T + b1) =====
        {
            const int m = tid & 127, q = tid >> 7;
            const float* x0 = xn + (2 * q) * KGP + 40;
            const float* x1 = x0 + KGP;
            ull a0 = 0ull, a1 = 0ull;
            #pragma unroll 4
            for (int k4 = 0; k4 < 64; ++k4) {
                const ulonglong2 wv = __ldg((const ulonglong2*)(W1_perm + ((k4 << 7) + m) * 4));
                const ulonglong2 p0 = *(const ulonglong2*)(x0 + 4 * k4);
                const ulonglong2 p1 = *(const ulonglong2*)(x1 + 4 * k4);
                fma2(a0, wv.x, p0.x); fma2(a0, wv.y, p0.y);
                fma2(a1, wv.x, p1.x); fma2(a1, wv.y, p1.y);
            }
            u1s[(2 * q) * US + m]     = fmaxf(hsum2(a0) + b1v, 0.f);
            u1s[(2 * q + 1) * US + m] = fmaxf(hsum2(a1) + b1v, 0.f);
        }
        __syncthreads();                            // sync 2

        // ===== MLP2 =====
        {
            const int m = tid & 127, q = tid >> 7;
            const float* x0 = u1s + (2 * q) * US;
            const float* x1 = x0 + US;
            ull a0 = 0ull, a1 = 0ull;
            #pragma unroll 4
            for (int k4 = 0; k4 < 32; ++k4) {
                const ulonglong2 wv = __ldg((const ulonglong2*)(W2_perm + ((k4 << 7) + m) * 4));
                const ulonglong2 p0 = *(const ulonglong2*)(x0 + 4 * k4);
                const ulonglong2 p1 = *(const ulonglong2*)(x1 + 4 * k4);
                fma2(a0, wv.x, p0.x); fma2(a0, wv.y, p0.y);
                fma2(a1, wv.x, p1.x); fma2(a1, wv.y, p1.y);
            }
            u2s[(2 * q) * US + m]     = fmaxf(hsum2(a0) + b2v, 0.f);
            u2s[(2 * q + 1) * US + m] = fmaxf(hsum2(a1) + b2v, 0.f);
        }
        __syncthreads();                            // sync 3

        // ===== merged zz + z: thread (r, j) computes loc (row j) AND raw (row j+32) =====
        if (tid < 256) {
            const int j = tid & 31, r = tid >> 5;
            const float* xp = u2s + r * US;
            ull a0 = 0ull, a1 = 0ull;
            #pragma unroll 4
            for (int k4 = 0; k4 < 32; ++k4) {
                const ulonglong2 w0 = __ldg((const ulonglong2*)(Wz_perm + ((k4 << 6) + j) * 4));
                const ulonglong2 w1 = __ldg((const ulonglong2*)(Wz_perm + ((k4 << 6) + 32 + j) * 4));
                const ulonglong2 pv = *(const ulonglong2*)(xp + 4 * k4);
                fma2(a0, w0.x, pv.x); fma2(a0, w0.y, pv.y);
                fma2(a1, w1.x, pv.x); fma2(a1, w1.y, pv.y);
            }
            float loc = hsum2(a0) + bz0;
            float sr  = hsum2(a1) + bz1;
            float sp  = (sr > 15.f) ? sr : log1pf(__expf(sr));
            float e   = eps[((n0 + r) * TT + t) * ZD + j];
            float zn  = fmaf(sp, e, loc);
            Z[((n0 + r) * TT + t) * ZD + j] = zn;
            xn[r * KGP + 8 + j] = zn;
        }
        __syncthreads();                            // sync 4: xn complete for next step
    }
}

extern "C" void kernel_launch(void* const* d_in, const int* in_sizes, int n_in,
                              void* d_out, int out_size) {
    const float* A    = (const float*)d_in[0];
    const float* eps  = (const float*)d_in[1];
    const float* z0   = (const float*)d_in[2];
    const float* h0   = (const float*)d_in[3];
    const float* c0   = (const float*)d_in[4];
    const float* W_ih = (const float*)d_in[5];
    const float* W_hh = (const float*)d_in[6];
    const float* b_ih = (const float*)d_in[7];
    const float* b_hh = (const float*)d_in[8];
    const float* W1   = (const float*)d_in[9];
    const float* b1   = (const float*)d_in[10];
    const float* W2   = (const float*)d_in[11];
    const float* b2   = (const float*)d_in[12];
    const float* Wz   = (const float*)d_in[13];
    const float* bz   = (const float*)d_in[14];

    permute_weights<<<148, 256>>>(W_ih, W_hh, W1, W2, Wz);
    lstm_guide_kernel<<<128, NT>>>(A, eps, z0, h0, c0,
                                   b_ih, b_hh, b1, b2, bz, (float*)d_out);
}

// round 10
// speedup vs baseline: 1.0067x; 1.0001x over previous
#include <cuda_runtime.h>
typedef unsigned long long ull;

#define TT 128
#define ZD 32
#define KG4 74
#define KGP 300   // xh row stride (floats): a 0..7 | z 8..39 | h 40..295
#define US 132
#define NT 512

__device__ __align__(16) float Wg_perm[KG4 * 1024 * 4];  // [k4][1024 rows][4]
__device__ __align__(16) float W1_perm[64 * 128 * 4];
__device__ __align__(16) float W2_perm[32 * 128 * 4];
__device__ __align__(16) float Wz_perm[32 * 64 * 4];

__device__ __forceinline__ void fma2(ull &d, ull a, ull b) {
    asm("fma.rn.f32x2 %0, %1, %2, %0;" : "+l"(d) : "l"(a), "l"(b));
}
__device__ __forceinline__ float hsum2(ull v) {
    float lo, hi; asm("mov.b64 {%0, %1}, %2;" : "=f"(lo), "=f"(hi) : "l"(v));
    return lo + hi;
}
__device__ __forceinline__ float fsig(float x) { return 1.f / (1.f + __expf(-x)); }
__device__ __forceinline__ float ftanh_(float x) { return fmaf(2.f, fsig(2.f * x), -1.f); }

__global__ void permute_weights(const float* __restrict__ W_ih, const float* __restrict__ W_hh,
                                const float* __restrict__ W1, const float* __restrict__ W2,
                                const float* __restrict__ Wz)
{
    const int stride = gridDim.x * blockDim.x;
    const int tid = blockIdx.x * blockDim.x + threadIdx.x;
    for (int i = tid; i < KG4 * 1024 * 4; i += stride) {
        int j = i & 3, R = (i >> 2) & 1023, k4 = i >> 12;
        int k = 4 * k4 + j;
        Wg_perm[i] = (k < 40) ? W_ih[R * 40 + k] : W_hh[R * 256 + (k - 40)];
    }
    for (int i = tid; i < 64 * 128 * 4; i += stride) {
        int j = i & 3, m = (i >> 2) & 127, k4 = i >> 9;
        W1_perm[i] = W1[m * 256 + 4 * k4 + j];
    }
    for (int i = tid; i < 32 * 128 * 4; i += stride) {
        int j = i & 3, m = (i >> 2) & 127, k4 = i >> 9;
        W2_perm[i] = W2[m * 128 + 4 * k4 + j];
    }
    for (int i = tid; i < 32 * 64 * 4; i += stride) {
        int j = i & 3, m = (i >> 2) & 63, k4 = i >> 8;
        Wz_perm[i] = Wz[m * 128 + 4 * k4 + j];
    }
}

#define LDW(dst, kk) do { \
    dst[0] = __ldg((const ulonglong2*)(wb + ((kk) * 1024 +   0) * 4)); \
    dst[1] = __ldg((const ulonglong2*)(wb + ((kk) * 1024 + 256) * 4)); \
    dst[2] = __ldg((const ulonglong2*)(wb + ((kk) * 1024 + 512) * 4)); \
    dst[3] = __ldg((const ulonglong2*)(wb + ((kk) * 1024 + 768) * 4)); \
} while (0)

#define GEMM4(W, kk) do { \
    _Pragma("unroll") \
    for (int j = 0; j < 4; ++j) { \
        const ulonglong2 xv = *(const ulonglong2*)(xc + (bq * 4 + j) * KGP + 4 * (kk)); \
        fma2(acc[0][j], W[0].x, xv.x); fma2(acc[0][j], W[0].y, xv.y); \
        fma2(acc[1][j], W[1].x, xv.x); fma2(acc[1][j], W[1].y, xv.y); \
        fma2(acc[2][j], W[2].x, xv.x); fma2(acc[2][j], W[2].y, xv.y); \
        fma2(acc[3][j], W[3].x, xv.x); fma2(acc[3][j], W[3].y, xv.y); \
    } \
} while (0)

// One CTA = 8 batch rows, 512 threads. Thread (hid=tid>>1, bq=tid&1) computes
// all 4 gates of `hid` for 4 batch rows. Ping-pong xh; 4 syncthreads/step.
__global__ void __launch_bounds__(NT, 1)
lstm_guide_kernel(const float* __restrict__ A, const float* __restrict__ eps,
                  const float* __restrict__ z0, const float* __restrict__ h0,
                  const float* __restrict__ c0, const float* __restrict__ b_ih,
                  const float* __restrict__ b_hh, const float* __restrict__ b1,
                  const float* __restrict__ b2, const float* __restrict__ bz,
                  float* __restrict__ Z)
{
    __shared__ __align__(16) float xh[2 * 8 * KGP];
    __shared__ __align__(16) float u1s[8 * US];
    __shared__ __align__(16) float u2s[8 * US];

    const int tid = threadIdx.x;
    const int n0 = blockIdx.x * 8;
    const int hid = tid >> 1, bq = tid & 1;

    const float bs0 = b_ih[hid]       + b_hh[hid];
    const float bs1 = b_ih[256 + hid] + b_hh[256 + hid];
    const float bs2 = b_ih[512 + hid] + b_hh[512 + hid];
    const float bs3 = b_ih[768 + hid] + b_hh[768 + hid];
    const float b1v = b1[tid & 127], b2v = b2[tid & 127];
    const float bz0 = bz[tid & 31], bz1 = bz[32 + (tid & 31)];

    for (int i = tid; i < 8 * 256; i += NT) {       // h0 -> buf0
        int b = i >> 8, k = i & 255;
        xh[b * KGP + 40 + k] = h0[k];
    }
    if (tid < 64) {                                 // a0
        int b = tid >> 3, k = tid & 7;
        xh[b * KGP + k] = A[((n0 + b) * TT) * 8 + k];
    } else if (tid < 320) {                         // z0
        int i = tid - 64, b = i >> 5, j = i & 31;
        xh[b * KGP + 8 + j] = z0[j];
    }
    float c_reg[4];
    #pragma unroll
    for (int j = 0; j < 4; ++j) c_reg[j] = c0[hid];
    __syncthreads();

    const float* wb = Wg_perm + hid * 4;

    for (int t = 0; t < TT; ++t) {
        float* xc = xh + (t & 1) * 8 * KGP;
        float* xn = xh + ((t + 1) & 1) * 8 * KGP;

        // ===== gates: software-pipelined weight prefetch =====
        ull acc[4][4];
        #pragma unroll
        for (int g = 0; g < 4; ++g)
            #pragma unroll
            for (int j = 0; j < 4; ++j) acc[g][j] = 0ull;

        ulonglong2 WA[4], WB[4];
        LDW(WA, 0);
        #pragma unroll 1
        for (int k4 = 0; k4 < KG4 - 2; k4 += 2) {
            LDW(WB, k4 + 1);
            GEMM4(WA, k4);
            LDW(WA, k4 + 2);
            GEMM4(WB, k4 + 1);
        }
        LDW(WB, KG4 - 1);
        GEMM4(WA, KG4 - 2);
        GEMM4(WB, KG4 - 1);

        // ===== LSTM cell (all 4 gates in-thread) =====
        float hv[4];
        #pragma unroll
        for (int j = 0; j < 4; ++j) {
            float iv = fsig(hsum2(acc[0][j]) + bs0);
            float fv = fsig(hsum2(acc[1][j]) + bs1);
            float gv = ftanh_(hsum2(acc[2][j]) + bs2);
            float ov = fsig(hsum2(acc[3][j]) + bs3);
            float c = fv * c_reg[j] + iv * gv;
            c_reg[j] = c;
            hv[j] = ov * ftanh_(c);
        }
        // h_{t+1} into NEXT buffer (no barrier needed before writes)
        #pragma unroll
        for (int j = 0; j < 4; ++j)
            xn[(bq * 4 + j) * KGP + 40 + hid] = hv[j];
        if (tid < 64 && t + 1 < TT) {               // a_{t+1} prefetch
            int b = tid >> 3, k = tid & 7;
            xn[b * KGP + k] = A[((n0 + b) * TT + t + 1) * 8 + k];
        }
        __syncthreads();                            // sync 1: h complete

        // ===== MLP1: relu(h @ W1^T + b1) =====
        {
            const int m = tid & 127, q = tid >> 7;
            const float* x0 = xn + (2 * q) * KGP + 40;
            const float* x1 = x0 + KGP;
            ull a0 = 0ull, a1 = 0ull;
            #pragma unroll 4
            for (int k4 = 0; k4 < 64; ++k4) {
                const ulonglong2 wv = __ldg((const ulonglong2*)(W1_perm + ((k4 << 7) + m) * 4));
                const ulonglong2 p0 = *(const ulonglong2*)(x0 + 4 * k4);
                const ulonglong2 p1 = *(const ulonglong2*)(x1 + 4 * k4);
                fma2(a0, wv.x, p0.x); fma2(a0, wv.y, p0.y);
                fma2(a1, wv.x, p1.x); fma2(a1, wv.y, p1.y);
            }
            u1s[(2 * q) * US + m]     = fmaxf(hsum2(a0) + b1v, 0.f);
            u1s[(2 * q + 1) * US + m] = fmaxf(hsum2(a1) + b1v, 0.f);
        }
        __syncthreads();                            // sync 2

        // ===== MLP2 =====
        {
            const int m = tid & 127, q = tid >> 7;
            const float* x0 = u1s + (2 * q) * US;
            const float* x1 = x0 + US;
            ull a0 = 0ull, a1 = 0ull;
            #pragma unroll 4
            for (int k4 = 0; k4 < 32; ++k4) {
                const ulonglong2 wv = __ldg((const ulonglong2*)(W2_perm + ((k4 << 7) + m) * 4));
                const ulonglong2 p0 = *(const ulonglong2*)(x0 + 4 * k4);
                const ulonglong2 p1 = *(const ulonglong2*)(x1 + 4 * k4);
                fma2(a0, wv.x, p0.x); fma2(a0, wv.y, p0.y);
                fma2(a1, wv.x, p1.x); fma2(a1, wv.y, p1.y);
            }
            u2s[(2 * q) * US + m]     = fmaxf(hsum2(a0) + b2v, 0.f);
            u2s[(2 * q + 1) * US + m] = fmaxf(hsum2(a1) + b2v, 0.f);
        }
        __syncthreads();                            // sync 3

        // ===== merged zz + z: thread (r, j) computes loc (row j) AND raw (row j+32) =====
        if (tid < 256) {
            const int j = tid & 31, r = tid >> 5;
            const float* xp = u2s + r * US;
            ull a0 = 0ull, a1 = 0ull;
            #pragma unroll 4
            for (int k4 = 0; k4 < 32; ++k4) {
                const ulonglong2 w0 = __ldg((const ulonglong2*)(Wz_perm + ((k4 << 6) + j) * 4));
                const ulonglong2 w1 = __ldg((const ulonglong2*)(Wz_perm + ((k4 << 6) + 32 + j) * 4));
                const ulonglong2 pv = *(const ulonglong2*)(xp + 4 * k4);
                fma2(a0, w0.x, pv.x); fma2(a0, w0.y, pv.y);
                fma2(a1, w1.x, pv.x); fma2(a1, w1.y, pv.y);
            }
            float loc = hsum2(a0) + bz0;
            float sr  = hsum2(a1) + bz1;
            float sp  = (sr > 15.f) ? sr : log1pf(__expf(sr));
            float e   = eps[((n0 + r) * TT + t) * ZD + j];
            float zn  = fmaf(sp, e, loc);
            Z[((n0 + r) * TT + t) * ZD + j] = zn;
            xn[r * KGP + 8 + j] = zn;
        }
        __syncthreads();                            // sync 4: xn complete for next step
    }
}

extern "C" void kernel_launch(void* const* d_in, const int* in_sizes, int n_in,
                              void* d_out, int out_size) {
    const float* A    = (const float*)d_in[0];
    const float* eps  = (const float*)d_in[1];
    const float* z0   = (const float*)d_in[2];
    const float* h0   = (const float*)d_in[3];
    const float* c0   = (const float*)d_in[4];
    const float* W_ih = (const float*)d_in[5];
    const float* W_hh = (const float*)d_in[6];
    const float* b_ih = (const float*)d_in[7];
    const float* b_hh = (const float*)d_in[8];
    const float* W1   = (const float*)d_in[9];
    const float* b1   = (const float*)d_in[10];
    const float* W2   = (const float*)d_in[11];
    const float* b2   = (const float*)d_in[12];
    const float* Wz   = (const float*)d_in[13];
    const float* bz   = (const float*)d_in[14];

    permute_weights<<<148, 256>>>(W_ih, W_hh, W1, W2, Wz);
    lstm_guide_kernel<<<128, NT>>>(A, eps, z0, h0, c0,
                                   b_ih, b_hh, b1, b2, bz, (float*)d_out);
}